// round 9
// baseline (speedup 1.0000x reference)
#include <cuda_runtime.h>
#include <cuda_bf16.h>
#include <cstdint>
#include <math.h>

#define B_TOK 8192
#define HDIM  7168
#define NEXP  256
#define NTOPK 8

#define BM 128
#define BN 128
#define BK 32
#define NT (HDIM / BK)          // 224

#define STRIDE 40               // smem row stride in bf16 elems (32 + 8 pad)
#define TILE 10240u             // one 128x32 bf16 tile (STRIDE rows), bytes
#define OFF_AHI 0u
#define OFF_ALO 10240u
#define OFF_BHI 20480u
#define OFF_BLO 30720u
#define STAGE_BYTES 40960u
#define SMEM_DYN (4u * STAGE_BYTES)     // 163840 (160 KB)

// ---- device scratch (no cudaMalloc allowed) ----
__device__ float         g_logits[(size_t)B_TOK * NEXP];
__device__ __nv_bfloat16 g_wt_hi[(size_t)NEXP * HDIM];     // W^T hi  [E][H]
__device__ __nv_bfloat16 g_wt_lo[(size_t)NEXP * HDIM];     // W^T lo  [E][H]
__device__ __nv_bfloat16 g_x_hi[(size_t)B_TOK * HDIM];     // x hi    [B][H]
__device__ __nv_bfloat16 g_x_lo[(size_t)B_TOK * HDIM];     // x lo    [B][H]

__device__ __forceinline__ uint32_t smem_u32(const void* p) {
    uint32_t a;
    asm("{ .reg .u64 t; cvta.to.shared.u64 t, %1; cvt.u32.u64 %0, t; }" : "=r"(a) : "l"(p));
    return a;
}

#define LDSM_X4(d, addr)                                                        \
    asm volatile("ldmatrix.sync.aligned.m8n8.x4.shared.b16 {%0,%1,%2,%3}, [%4];"\
        : "=r"((d)[0]), "=r"((d)[1]), "=r"((d)[2]), "=r"((d)[3]) : "r"(addr))

#define MMA_BF16(c, a, b)                                                       \
    asm volatile("mma.sync.aligned.m16n8k16.row.col.f32.bf16.bf16.f32 "         \
        "{%0,%1,%2,%3}, {%4,%5,%6,%7}, {%8,%9}, {%0,%1,%2,%3};"                 \
        : "+f"((c)[0]), "+f"((c)[1]), "+f"((c)[2]), "+f"((c)[3])                \
        : "r"((a)[0]), "r"((a)[1]), "r"((a)[2]), "r"((a)[3]),                   \
          "r"((b)[0]), "r"((b)[1]))

#define CP16(dst, src)                                                          \
    asm volatile("cp.async.cg.shared.global [%0], [%1], 16;"                    \
                 :: "r"(dst), "l"(src) : "memory")
#define CP_COMMIT() asm volatile("cp.async.commit_group;" ::: "memory")
#define CP_WAIT2()  asm volatile("cp.async.wait_group 2;" ::: "memory")

// split 8 consecutive fp32 into 8 bf16 hi + 8 bf16 lo (packed)
__device__ __forceinline__ void split8(const float4 a, const float4 b,
                                       uint4& h, uint4& l) {
    __nv_bfloat162 h0 = __floats2bfloat162_rn(a.x, a.y);
    __nv_bfloat162 h1 = __floats2bfloat162_rn(a.z, a.w);
    __nv_bfloat162 h2 = __floats2bfloat162_rn(b.x, b.y);
    __nv_bfloat162 h3 = __floats2bfloat162_rn(b.z, b.w);
    float2 f0 = __bfloat1622float2(h0), f1 = __bfloat1622float2(h1);
    float2 f2 = __bfloat1622float2(h2), f3 = __bfloat1622float2(h3);
    __nv_bfloat162 l0 = __floats2bfloat162_rn(a.x - f0.x, a.y - f0.y);
    __nv_bfloat162 l1 = __floats2bfloat162_rn(a.z - f1.x, a.w - f1.y);
    __nv_bfloat162 l2 = __floats2bfloat162_rn(b.x - f2.x, b.y - f2.y);
    __nv_bfloat162 l3 = __floats2bfloat162_rn(b.z - f3.x, b.w - f3.y);
    h.x = *(uint32_t*)&h0; h.y = *(uint32_t*)&h1;
    h.z = *(uint32_t*)&h2; h.w = *(uint32_t*)&h3;
    l.x = *(uint32_t*)&l0; l.y = *(uint32_t*)&l1;
    l.z = *(uint32_t*)&l2; l.w = *(uint32_t*)&l3;
}

// ---------------------------------------------------------------------------
// Prep x: stream-split x fp32 -> x_hi/x_lo bf16 (8 elems/thread)
// ---------------------------------------------------------------------------
__global__ __launch_bounds__(256) void prep_x_kernel(const float* __restrict__ x) {
    const size_t i = ((size_t)blockIdx.x * 256 + threadIdx.x) * 8;
    const float4 a = *(const float4*)(x + i);
    const float4 b = *(const float4*)(x + i + 4);
    uint4 h, l;
    split8(a, b, h, l);
    *(uint4*)(g_x_hi + i) = h;
    *(uint4*)(g_x_lo + i) = l;
}

// ---------------------------------------------------------------------------
// Prep W: transpose + bf16-split W[H,E] -> Wt_hi/Wt_lo [E][H]
// ---------------------------------------------------------------------------
__global__ void prep_w_kernel(const float* __restrict__ w) {
    __shared__ float t[32][33];
    const int k0 = blockIdx.x * 32, e0 = blockIdx.y * 32;
    const int tx = threadIdx.x, ty = threadIdx.y;
#pragma unroll
    for (int i = 0; i < 4; i++)
        t[ty + i * 8][tx] = w[(size_t)(k0 + ty + i * 8) * NEXP + e0 + tx];
    __syncthreads();
#pragma unroll
    for (int i = 0; i < 4; i++) {
        const int e = e0 + ty + i * 8, k = k0 + tx;
        const float v = t[tx][ty + i * 8];
        const __nv_bfloat16 h = __float2bfloat16(v);
        g_wt_hi[(size_t)e * HDIM + k] = h;
        g_wt_lo[(size_t)e * HDIM + k] = __float2bfloat16(v - __bfloat162float(h));
    }
}

// ---------------------------------------------------------------------------
// GEMM: logits = x @ W via mma.sync bf16 (3-term split), BK=32.
// ALL operands pre-split bf16 in gmem; hot loop is pure cp.async + LDSM + MMA.
// 4-stage ring, prefetch distance 2, wait_group 2.
// ---------------------------------------------------------------------------
__global__ __launch_bounds__(256, 1) void gemm_mma_kernel()
{
    extern __shared__ __nv_bfloat16 smem[];
    const uint32_t sb = smem_u32(smem);

    const int tid  = threadIdx.x;
    const int lane = tid & 31;
    const int wid  = tid >> 5;
    const int row0 = blockIdx.x * BM;
    const int col0 = blockIdx.y * BN;

    const int wm = (wid & 1) * 64;     // warp M base
    const int wn = (wid >> 1) * 32;    // warp N base

    // cp.async mapping: thread covers 16 elems (32 B) of one row
    const int r   = tid >> 1;          // 0..127
    const int c16 = (tid & 1) * 16;    // 0 or 16
    const __nv_bfloat16* xhrow = g_x_hi  + (size_t)(row0 + r) * HDIM + c16;
    const __nv_bfloat16* xlrow = g_x_lo  + (size_t)(row0 + r) * HDIM + c16;
    const __nv_bfloat16* whrow = g_wt_hi + (size_t)(col0 + r) * HDIM + c16;
    const __nv_bfloat16* wlrow = g_wt_lo + (size_t)(col0 + r) * HDIM + c16;
    const uint32_t st_off = ((uint32_t)r * STRIDE + (uint32_t)c16) * 2;  // bytes

    // ldmatrix byte offsets (stage-relative)
    uint32_t aoff[4], boff[2];
    {
        const int ar = wm + (lane & 15);
        const int ac = (lane >> 4) * 8;
#pragma unroll
        for (int mt = 0; mt < 4; mt++)
            aoff[mt] = (uint32_t)(OFF_AHI + ((ar + mt * 16) * STRIDE + ac) * 2);
        const int brr = (lane & 7) + ((lane >> 4) & 1) * 8;
        const int bc  = ((lane >> 3) & 1) * 8;
#pragma unroll
        for (int p = 0; p < 2; p++)
            boff[p] = (uint32_t)(OFF_BHI + ((wn + p * 16 + brr) * STRIDE + bc) * 2);
    }

    float acc[4][4][4];
#pragma unroll
    for (int i = 0; i < 4; i++)
#pragma unroll
        for (int j = 0; j < 4; j++)
#pragma unroll
            for (int q = 0; q < 4; q++) acc[i][j][q] = 0.0f;

    auto cp_stage = [&](int stage, int t) {
        const uint32_t d = sb + (uint32_t)stage * STAGE_BYTES + st_off;
        const char* axh = (const char*)(xhrow + t * BK);
        const char* axl = (const char*)(xlrow + t * BK);
        const char* bwh = (const char*)(whrow + t * BK);
        const char* bwl = (const char*)(wlrow + t * BK);
        CP16(d + OFF_AHI,      axh); CP16(d + OFF_AHI + 16, axh + 16);
        CP16(d + OFF_ALO,      axl); CP16(d + OFF_ALO + 16, axl + 16);
        CP16(d + OFF_BHI,      bwh); CP16(d + OFF_BHI + 16, bwh + 16);
        CP16(d + OFF_BLO,      bwl); CP16(d + OFF_BLO + 16, bwl + 16);
    };

    // ---- prologue: stages 0,1 in flight ----
    cp_stage(0, 0); CP_COMMIT();
    cp_stage(1, 1); CP_COMMIT();

    // ---- main loop ----
    for (int t = 0; t < NT; ++t) {
        if (t + 2 < NT) cp_stage((t + 2) & 3, t + 2);
        CP_COMMIT();            // unconditional: group indexing stays aligned
        CP_WAIT2();             // stage t drained; t+1, t+2 may remain
        __syncthreads();

        const uint32_t sbase = sb + (uint32_t)(t & 3) * STAGE_BYTES;
#pragma unroll
        for (int ks = 0; ks < 2; ks++) {
            uint32_t a_hi[4][4], a_lo[4][4], b_hi[2][4], b_lo[2][4];
#pragma unroll
            for (int mt = 0; mt < 4; mt++) {
                LDSM_X4(a_hi[mt], sbase + aoff[mt] + ks * 32);
                LDSM_X4(a_lo[mt], sbase + aoff[mt] + ks * 32 + (OFF_ALO - OFF_AHI));
            }
#pragma unroll
            for (int p = 0; p < 2; p++) {
                LDSM_X4(b_hi[p], sbase + boff[p] + ks * 32);
                LDSM_X4(b_lo[p], sbase + boff[p] + ks * 32 + (OFF_BLO - OFF_BHI));
            }
#pragma unroll
            for (int mt = 0; mt < 4; mt++)
#pragma unroll
                for (int nt = 0; nt < 4; nt++) {
                    MMA_BF16(acc[mt][nt], a_hi[mt], &b_hi[nt >> 1][(nt & 1) * 2]);
                    MMA_BF16(acc[mt][nt], a_lo[mt], &b_hi[nt >> 1][(nt & 1) * 2]);
                    MMA_BF16(acc[mt][nt], a_hi[mt], &b_lo[nt >> 1][(nt & 1) * 2]);
                }
        }
        __syncthreads();        // readers done before stage reuse next iters
    }

    // ---- epilogue: accumulators -> g_logits ----
    const int erow = lane >> 2;             // 0..7
    const int ecol = (lane & 3) * 2;        // 0,2,4,6
#pragma unroll
    for (int mt = 0; mt < 4; mt++) {
        const int rbase = row0 + wm + mt * 16 + erow;
#pragma unroll
        for (int nt = 0; nt < 4; nt++) {
            const int c = col0 + wn + nt * 8 + ecol;
            float* d0 = g_logits + (size_t)rbase * NEXP + c;
            float* d1 = d0 + 8 * NEXP;
            d0[0] = acc[mt][nt][0]; d0[1] = acc[mt][nt][1];
            d1[0] = acc[mt][nt][2]; d1[1] = acc[mt][nt][3];
        }
    }
}

// ---------------------------------------------------------------------------
// Routing: one warp per token; expert e = j*32 + lane (slot j == group j).
// Reproduces jax.lax.top_k tie-break (lower index wins).
// ---------------------------------------------------------------------------
__global__ __launch_bounds__(256) void route_kernel(
    const float* __restrict__ bias, float* __restrict__ out)
{
    __shared__ float s_sh[8][NEXP];

    const int lane = threadIdx.x & 31;
    const int wrp  = threadIdx.x >> 5;
    const int t    = blockIdx.x * 8 + wrp;

    const float* lrow = g_logits + (size_t)t * NEXP;

    float v[8];
#pragma unroll
    for (int j = 0; j < 8; j++) v[j] = lrow[j * 32 + lane];

    float m = v[0];
#pragma unroll
    for (int j = 1; j < 8; j++) m = fmaxf(m, v[j]);
    for (int off = 16; off; off >>= 1)
        m = fmaxf(m, __shfl_xor_sync(0xffffffffu, m, off));

    float sum = 0.0f;
#pragma unroll
    for (int j = 0; j < 8; j++) { v[j] = __expf(v[j] - m); sum += v[j]; }
    for (int off = 16; off; off >>= 1)
        sum += __shfl_xor_sync(0xffffffffu, sum, off);
    const float inv = 1.0f / sum;

    float s[8], swb[8];
#pragma unroll
    for (int j = 0; j < 8; j++) {
        s[j] = v[j] * inv;
        s_sh[wrp][j * 32 + lane] = s[j];
        swb[j] = s[j] + bias[j * 32 + lane];
    }

    // group scores: top-2 sum within each 32-lane group
    float gs[8];
#pragma unroll
    for (int j = 0; j < 8; j++) {
        float hi = swb[j], lo = -INFINITY;
        for (int off = 16; off; off >>= 1) {
            float ohi = __shfl_xor_sync(0xffffffffu, hi, off);
            float olo = __shfl_xor_sync(0xffffffffu, lo, off);
            float nh = fmaxf(hi, ohi);
            float nl = fmaxf(fminf(hi, ohi), fmaxf(lo, olo));
            hi = nh; lo = nl;
        }
        gs[j] = hi + lo;
    }

    // top-4 groups by rank
    float mk[8];
#pragma unroll
    for (int g = 0; g < 8; g++) {
        int rank = 0;
#pragma unroll
        for (int k2 = 0; k2 < 8; k2++)
            if (gs[k2] > gs[g] || (gs[k2] == gs[g] && k2 < g)) rank++;
        mk[g] = (rank < 4) ? swb[g] : -INFINITY;
    }

    // iterative top-8
    float myv = 0.0f;
    int   myi = 0;
    float tot = 0.0f;
#pragma unroll
    for (int it = 0; it < NTOPK; it++) {
        float bv = mk[0];
        int   bi = lane;
#pragma unroll
        for (int j = 1; j < 8; j++) {
            const int idx = j * 32 + lane;
            if (mk[j] > bv || (mk[j] == bv && idx < bi)) { bv = mk[j]; bi = idx; }
        }
        for (int off = 16; off; off >>= 1) {
            float ov = __shfl_xor_sync(0xffffffffu, bv, off);
            int   oi = __shfl_xor_sync(0xffffffffu, bi, off);
            if (ov > bv || (ov == bv && oi < bi)) { bv = ov; bi = oi; }
        }
        const float ws = s_sh[wrp][bi];
        tot += ws;
        if (lane == it) { myv = ws; myi = bi; }
        if ((bi & 31) == lane) {
            const int jj = bi >> 5;
#pragma unroll
            for (int j = 0; j < 8; j++)
                if (j == jj) mk[j] = -INFINITY;
        }
    }

    const float itot = 1.0f / tot;
    if (lane < NTOPK) {
        out[(size_t)t * NTOPK + lane] = (myv * itot + 1e-20f) * 2.5f;
        out[(size_t)B_TOK * NTOPK + (size_t)t * NTOPK + lane] = (float)myi;
    }
}

// ---------------------------------------------------------------------------
extern "C" void kernel_launch(void* const* d_in, const int* in_sizes, int n_in,
                              void* d_out, int out_size)
{
    const float* x    = (const float*)d_in[0];   // [1,1,B,H]
    const float* w    = (const float*)d_in[1];   // [H,E]
    const float* bias = (const float*)d_in[2];   // [E]
    float* out = (float*)d_out;

    (void)cudaFuncSetAttribute(gemm_mma_kernel,
                               cudaFuncAttributeMaxDynamicSharedMemorySize, SMEM_DYN);

    prep_x_kernel<<<(B_TOK * HDIM) / (256 * 8), 256>>>(x);
    prep_w_kernel<<<dim3(HDIM / 32, NEXP / 32), dim3(32, 8)>>>(w);
    gemm_mma_kernel<<<dim3(B_TOK / BM, NEXP / BN), 256, SMEM_DYN>>>();
    route_kernel<<<B_TOK / 8, 256>>>(bias, out);
}